// round 15
// baseline (speedup 1.0000x reference)
#include <cuda_runtime.h>
#include <cstdint>

// pred/target: [16,1,1024,1024] float32.
#define H 1024
#define W 1024
#define TOTAL (16u * 1024u * 1024u)
#define ROWS_PER_BLOCK 16
#define THREADS_B 256
#define GRID_B 1024            // 16*1024 rows / 16 -> single wave (<1184 slots)
#define BLOCKS_PER_IMG 64      // 1024 / 16

__device__ float g_partials[GRID_B];
__device__ unsigned g_done = 0;     // completion counter; reset by last block

__device__ __forceinline__ uint4 load_u4(const float* p) {
    float4 f = *reinterpret_cast<const float4*>(p);
    uint4 u;
    u.x = __float_as_uint(f.x); u.y = __float_as_uint(f.y);
    u.z = __float_as_uint(f.z); u.w = __float_as_uint(f.w);
    return u;
}

// weighted BCE-with-logits for one element.
// losses = w * softplus(x*(1-2t)),  w = 1 + 4*dil + 15*t  (t,dil in {0,1})
__device__ __forceinline__ float elem_loss(float x, unsigned tbits, unsigned dbits,
                                           float acc) {
    float t   = __uint_as_float(tbits);
    float dil = __uint_as_float(dbits);
    float z   = x * fmaf(t, -2.0f, 1.0f);
    float e   = __expf(-fabsf(z));          // FMUL + MUFU.EX2
    float l   = __logf(1.0f + e);           // FADD + MUFU.LG2 + FMUL
    float sp  = fmaxf(z, 0.0f) + l;
    float w   = fmaf(t, 15.0f, fmaf(dil, 4.0f, 1.0f));
    return fmaf(w, sp, acc);
}

__global__ void __launch_bounds__(THREADS_B)
main_kernel(const float* __restrict__ pred, const float* __restrict__ target,
            float* __restrict__ out) {
    __shared__ float sred[THREADS_B / 32];
    __shared__ bool  s_last;

    const int tid  = threadIdx.x;
    const int bid  = blockIdx.x;
    const int lane = tid & 31;

    const int  rblk = bid & (BLOCKS_PER_IMG - 1);
    const bool topB = (rblk == 0);
    const bool botB = (rblk == BLOCKS_PER_IMG - 1);

    const bool lL = (lane == 0);
    const bool lR = (lane == 31);
    const bool haloL = lL && (tid != 0);               // needs left halo load
    const bool haloR = lR && (tid != THREADS_B - 1);   // needs right halo load

    // bid*16384 + tid*4 == img*1M + r0*W + col
    const size_t base = (size_t)bid * (ROWS_PER_BLOCK * W) + (size_t)tid * 4;
    const float* tg = target + base;   // advances one row per iteration
    const float* pr = pred   + base;

    // rolling raw target rows (bit-patterns; values are exactly 0.0f / 1.0f)
    uint4 tp, tc, tn;
    tc = load_u4(tg);
    tp = topB ? tc : load_u4(tg - W);

    // rolling halo scalars for warp-edge lanes (column tid*4-1 / tid*4+4)
    unsigned sLp = 0u, sLc = 0u, sLn = 0u;
    unsigned sRp = 0u, sRc = 0u, sRn = 0u;
    if (haloL) {
        sLc = __float_as_uint(tg[-1]);
        sLp = topB ? sLc : __float_as_uint(tg[-1 - W]);
    }
    if (haloR) {
        sRc = __float_as_uint(tg[4]);
        sRp = topB ? sRc : __float_as_uint(tg[4 - W]);
    }

    float acc = 0.0f;

    // one row of work given current window (tp,tc,tn) + pred row p
#define ROW_BODY()                                                         \
    do {                                                                   \
        uint4 v;                                                           \
        v.x = tp.x | tc.x | tn.x;                                          \
        v.y = tp.y | tc.y | tn.y;                                          \
        v.z = tp.z | tc.z | tn.z;                                          \
        v.w = tp.w | tc.w | tn.w;                                          \
        unsigned vLs = __shfl_up_sync(0xffffffffu, v.w, 1);                \
        unsigned vRs = __shfl_down_sync(0xffffffffu, v.x, 1);              \
        unsigned vL = lL ? (sLp | sLc | sLn) : vLs;                        \
        unsigned vR = lR ? (sRp | sRc | sRn) : vRs;                        \
        unsigned d0 = vL  | v.x | v.y;                                     \
        unsigned d1 = v.x | v.y | v.z;                                     \
        unsigned d2 = v.y | v.z | v.w;                                     \
        unsigned d3 = v.z | v.w | vR;                                      \
        acc = elem_loss(p.x, tc.x, d0, acc);                               \
        acc = elem_loss(p.y, tc.y, d1, acc);                               \
        acc = elem_loss(p.z, tc.z, d2, acc);                               \
        acc = elem_loss(p.w, tc.w, d3, acc);                               \
        tp = tc; tc = tn;                                                  \
        sLp = sLc; sLc = sLn;                                              \
        sRp = sRc; sRc = sRn;                                              \
    } while (0)

    // rows 0..14: next row always exists within the image
#pragma unroll 5
    for (int i = 0; i < ROWS_PER_BLOCK - 1; i++) {
        tn = load_u4(tg + W);
        if (haloL) sLn = __float_as_uint(tg[W - 1]);
        if (haloR) sRn = __float_as_uint(tg[W + 4]);
        float4 p = __ldcs(reinterpret_cast<const float4*>(pr));
        ROW_BODY();
        tg += W; pr += W;
    }

    // row 15: clamp at image bottom (duplicate current row)
    {
        if (botB) {
            tn = tc; sLn = sLc; sRn = sRc;
        } else {
            tn = load_u4(tg + W);
            sLn = haloL ? __float_as_uint(tg[W - 1]) : 0u;
            sRn = haloR ? __float_as_uint(tg[W + 4]) : 0u;
        }
        float4 p = __ldcs(reinterpret_cast<const float4*>(pr));
        ROW_BODY();
    }
#undef ROW_BODY

    // block reduction: warp shuffle tree, then one smem stage (deterministic)
#pragma unroll
    for (int s = 16; s > 0; s >>= 1)
        acc += __shfl_down_sync(0xffffffffu, acc, s);
    if (lane == 0) sred[tid >> 5] = acc;
    __syncthreads();
    if (tid == 0) {
        float r = 0.0f;
#pragma unroll
        for (int wrp = 0; wrp < THREADS_B / 32; wrp++) r += sred[wrp];
        g_partials[bid] = r;
        __threadfence();                       // publish partial before counting
        unsigned prev = atomicAdd(&g_done, 1u);
        s_last = (prev == GRID_B - 1u);
    }
    __syncthreads();

    // last block to finish folds the 1024 partials (fixed order -> deterministic)
    if (s_last) {
        float r = 0.0f;
#pragma unroll
        for (int k = 0; k < GRID_B / THREADS_B; k++)
            r += __ldcg(&g_partials[tid + k * THREADS_B]);   // L2-fresh reads
#pragma unroll
        for (int s = 16; s > 0; s >>= 1)
            r += __shfl_down_sync(0xffffffffu, r, s);
        if (lane == 0) sred[tid >> 5] = r;
        __syncthreads();
        if (tid == 0) {
            float tot = 0.0f;
#pragma unroll
            for (int wrp = 0; wrp < THREADS_B / 32; wrp++) tot += sred[wrp];
            out[0] = tot * (1.0f / (float)TOTAL);
            g_done = 0;                        // reset for next graph replay
        }
    }
}

extern "C" void kernel_launch(void* const* d_in, const int* in_sizes, int n_in,
                              void* d_out, int out_size) {
    const float* pred   = (const float*)d_in[0];
    const float* target = (const float*)d_in[1];
    (void)in_sizes; (void)n_in; (void)out_size;

    main_kernel<<<GRID_B, THREADS_B>>>(pred, target, (float*)d_out);
}

// round 16
// speedup vs baseline: 1.2031x; 1.2031x over previous
#include <cuda_runtime.h>
#include <cstdint>

// pred/target: [16,1,1024,1024] float32.
#define H 1024
#define W 1024
#define TOTAL (16u * 1024u * 1024u)
#define ROWS_PER_BLOCK 8
#define THREADS_B 256
#define GRID_B 2048            // 16*1024 rows / 8 rows per block
#define BLOCKS_PER_IMG 128     // 1024 / 8

__device__ float g_partials[GRID_B];
__device__ unsigned g_done = 0;     // completion counter; reset by last block

__device__ __forceinline__ uint4 load_u4(const float* p) {
    float4 f = *reinterpret_cast<const float4*>(p);
    uint4 u;
    u.x = __float_as_uint(f.x); u.y = __float_as_uint(f.y);
    u.z = __float_as_uint(f.z); u.w = __float_as_uint(f.w);
    return u;
}

// weighted BCE-with-logits for one element.
// losses = w * softplus(x*(1-2t)),  w = 1 + 4*dil + 15*t  (t,dil in {0,1})
__device__ __forceinline__ float elem_loss(float x, unsigned tbits, unsigned dbits,
                                           float acc) {
    float t   = __uint_as_float(tbits);
    float dil = __uint_as_float(dbits);
    float z   = x * fmaf(t, -2.0f, 1.0f);
    float e   = __expf(-fabsf(z));          // FMUL + MUFU.EX2
    float l   = __logf(1.0f + e);           // FADD + MUFU.LG2 + FMUL
    float sp  = fmaxf(z, 0.0f) + l;
    float w   = fmaf(t, 15.0f, fmaf(dil, 4.0f, 1.0f));
    return fmaf(w, sp, acc);
}

__global__ void __launch_bounds__(THREADS_B)
main_kernel(const float* __restrict__ pred, const float* __restrict__ target,
            float* __restrict__ out) {
    __shared__ float sred[THREADS_B / 32];
    __shared__ bool  s_last;

    const int tid  = threadIdx.x;
    const int bid  = blockIdx.x;
    const int lane = tid & 31;

    const int  rblk = bid & (BLOCKS_PER_IMG - 1);
    const bool topB = (rblk == 0);
    const bool botB = (rblk == BLOCKS_PER_IMG - 1);

    const bool lL = (lane == 0);
    const bool lR = (lane == 31);
    const bool iL = (tid == 0);                 // image left edge column
    const bool iR = (tid == THREADS_B - 1);     // image right edge column

    // bid*8192 + tid*4 == img*1M + r0*W + col
    const size_t base = (size_t)bid * (ROWS_PER_BLOCK * W) + (size_t)tid * 4;
    const float* tg = target + base;
    const float* pr = pred   + base;

    // rolling raw target rows (bit-patterns; values are exactly 0.0f / 1.0f)
    uint4 tp, tc, tn;
    tc = load_u4(tg);
    tp = topB ? tc : load_u4(tg - W);

    // rolling halo scalars for warp-edge lanes (column tid*4-1 / tid*4+4)
    unsigned sLp = 0u, sLc = 0u, sLn = 0u;
    unsigned sRp = 0u, sRc = 0u, sRn = 0u;
    if (lL && !iL) {
        sLc = __float_as_uint(tg[-1]);
        sLp = topB ? sLc : __float_as_uint(tg[-1 - W]);
    }
    if (lR && !iR) {
        sRc = __float_as_uint(tg[4]);
        sRp = topB ? sRc : __float_as_uint(tg[4 - W]);
    }

    float acc = 0.0f;

#pragma unroll
    for (int i = 0; i < ROWS_PER_BLOCK; i++) {
        // next target row (clamped at image bottom; only reachable when i==7)
        const int nOff = (i == ROWS_PER_BLOCK - 1 && botB) ? i * W : (i + 1) * W;
        const float* tgn = tg + nOff;
        tn = load_u4(tgn);
        if (lL && !iL) sLn = __float_as_uint(tgn[-1]);
        if (lR && !iR) sRn = __float_as_uint(tgn[4]);

        // pred row (streaming: single-use, evict-first)
        float4 p = __ldcs(reinterpret_cast<const float4*>(pr + i * W));

        // vertical OR == 3-row max for {0.0f,1.0f} bit patterns (LOP3)
        uint4 v;
        v.x = tp.x | tc.x | tn.x;
        v.y = tp.y | tc.y | tn.y;
        v.z = tp.z | tc.z | tn.z;
        v.w = tp.w | tc.w | tn.w;

        // horizontal neighbors across lanes
        unsigned vLs = __shfl_up_sync(0xffffffffu, v.w, 1);
        unsigned vRs = __shfl_down_sync(0xffffffffu, v.x, 1);
        unsigned vL = lL ? (sLp | sLc | sLn) : vLs;   // zeros at image edge
        unsigned vR = lR ? (sRp | sRc | sRn) : vRs;

        // full 3x3 dilation bits
        unsigned d0 = vL  | v.x | v.y;
        unsigned d1 = v.x | v.y | v.z;
        unsigned d2 = v.y | v.z | v.w;
        unsigned d3 = v.z | v.w | vR;

        acc = elem_loss(p.x, tc.x, d0, acc);
        acc = elem_loss(p.y, tc.y, d1, acc);
        acc = elem_loss(p.z, tc.z, d2, acc);
        acc = elem_loss(p.w, tc.w, d3, acc);

        // roll windows (full unroll -> register renaming, no MOVs)
        tp = tc; tc = tn;
        sLp = sLc; sLc = sLn;
        sRp = sRc; sRc = sRn;
    }

    // block reduction: warp shuffle tree, then one smem stage (deterministic)
#pragma unroll
    for (int s = 16; s > 0; s >>= 1)
        acc += __shfl_down_sync(0xffffffffu, acc, s);
    if (lane == 0) sred[tid >> 5] = acc;
    __syncthreads();
    if (tid == 0) {
        float r = 0.0f;
#pragma unroll
        for (int wrp = 0; wrp < THREADS_B / 32; wrp++) r += sred[wrp];
        g_partials[bid] = r;
        __threadfence();                       // publish partial before counting
        unsigned prev = atomicAdd(&g_done, 1u);
        s_last = (prev == GRID_B - 1u);
    }
    __syncthreads();

    // last block to finish folds the 2048 partials (fixed order -> deterministic)
    if (s_last) {
        float r = 0.0f;
#pragma unroll
        for (int k = 0; k < GRID_B / THREADS_B; k++)
            r += __ldcg(&g_partials[tid + k * THREADS_B]);   // L2-fresh reads
#pragma unroll
        for (int s = 16; s > 0; s >>= 1)
            r += __shfl_down_sync(0xffffffffu, r, s);
        if (lane == 0) sred[tid >> 5] = r;
        __syncthreads();
        if (tid == 0) {
            float tot = 0.0f;
#pragma unroll
            for (int wrp = 0; wrp < THREADS_B / 32; wrp++) tot += sred[wrp];
            out[0] = tot * (1.0f / (float)TOTAL);
            g_done = 0;                        // reset for next graph replay
        }
    }
}

extern "C" void kernel_launch(void* const* d_in, const int* in_sizes, int n_in,
                              void* d_out, int out_size) {
    const float* pred   = (const float*)d_in[0];
    const float* target = (const float*)d_in[1];
    (void)in_sizes; (void)n_in; (void)out_size;

    main_kernel<<<GRID_B, THREADS_B>>>(pred, target, (float*)d_out);
}